// round 1
// baseline (speedup 1.0000x reference)
#include <cuda_runtime.h>
#include <math.h>
#include <float.h>

#define TPB 256
#define RN 8
#define TN (TPB * RN)   // 2048 query points per block
#define CH 224          // reference-point chunk staged in smem (even!)
#define MAXPTS (4 * 8192)

// Scratch: per-point min squared distances (no cudaMalloc allowed).
__device__ float g_min0[MAXPTS];  // min over cloud1 for each point of cloud2
__device__ float g_min1[MAXPTS];  // min over cloud2 for each point of cloud1

// ---------- packed f32x2 helpers ----------
__device__ __forceinline__ unsigned long long packdup(float x) {
    unsigned long long r;
    asm("mov.b64 %0, {%1, %1};" : "=l"(r) : "f"(x));
    return r;
}
__device__ __forceinline__ unsigned long long add2(unsigned long long a, unsigned long long b) {
    unsigned long long d;
    asm("add.rn.f32x2 %0, %1, %2;" : "=l"(d) : "l"(a), "l"(b));
    return d;
}
__device__ __forceinline__ unsigned long long mul2(unsigned long long a, unsigned long long b) {
    unsigned long long d;
    asm("mul.rn.f32x2 %0, %1, %2;" : "=l"(d) : "l"(a), "l"(b));
    return d;
}
__device__ __forceinline__ unsigned long long fma2(unsigned long long a, unsigned long long b,
                                                   unsigned long long c) {
    unsigned long long d;
    asm("fma.rn.f32x2 %0, %1, %2, %3;" : "=l"(d) : "l"(a), "l"(b), "l"(c));
    return d;
}
__device__ __forceinline__ void unpack2(unsigned long long v, float& lo, float& hi) {
    asm("mov.b64 {%0, %1}, %2;" : "=f"(lo), "=f"(hi) : "l"(v));
}

// ---------- init: fill min arrays with +FLT_MAX ----------
__global__ void init_kernel(int n0, int n1) {
    int i = blockIdx.x * blockDim.x + threadIdx.x;
    if (i < n0) g_min0[i] = FLT_MAX;
    if (i < n1) g_min1[i] = FLT_MAX;
}

// ---------- main pass: for each query point, min_{refs in chunk} ||q - r||^2 ----------
// which == 1 -> write g_min1, which == 0 -> write g_min0
__global__ __launch_bounds__(TPB) void pass_kernel(const float* __restrict__ Q,
                                                   const float* __restrict__ R,
                                                   int Nq, int Mr, int which) {
    __shared__ __align__(16) float nx[CH];
    __shared__ __align__(16) float ny[CH];
    __shared__ __align__(16) float nz[CH];

    const int b = blockIdx.z;
    const int mStart = blockIdx.y * CH;
    int cnt = Mr - mStart;
    if (cnt > CH) cnt = CH;
    if (cnt < 0) cnt = 0;
    const int tid = threadIdx.x;

    // Stage NEGATED reference chunk (so packed subtraction becomes add.rn.f32x2).
    for (int i = tid; i < cnt; i += TPB) {
        const float* p = R + ((size_t)b * Mr + mStart + i) * 3;
        nx[i] = -p[0];
        ny[i] = -p[1];
        nz[i] = -p[2];
    }
    __syncthreads();

    // Load RN query points per thread, coords duplicated into f32x2 pairs.
    const int nBase = blockIdx.x * TN;
    unsigned long long ax[RN], ay[RN], az[RN];
    float mn[RN];
    int nIdx[RN];
#pragma unroll
    for (int r = 0; r < RN; r++) {
        const int n = nBase + r * TPB + tid;
        nIdx[r] = n;
        float x = 0.f, y = 0.f, z = 0.f;
        if (n < Nq) {
            const float* p = Q + ((size_t)b * Nq + n) * 3;
            x = p[0]; y = p[1]; z = p[2];
        }
        ax[r] = packdup(x);
        ay[r] = packdup(y);
        az[r] = packdup(z);
        mn[r] = FLT_MAX;
    }

    const unsigned long long* px = (const unsigned long long*)nx;
    const unsigned long long* py = (const unsigned long long*)ny;
    const unsigned long long* pz = (const unsigned long long*)nz;

    const int pairs = cnt >> 1;
    for (int j = 0; j < pairs; j++) {
        const unsigned long long bx = px[j];  // LDS.64 broadcast (uniform addr)
        const unsigned long long by = py[j];
        const unsigned long long bz = pz[j];
#pragma unroll
        for (int r = 0; r < RN; r++) {
            unsigned long long dx = add2(ax[r], bx);
            unsigned long long dy = add2(ay[r], by);
            unsigned long long dz = add2(az[r], bz);
            unsigned long long s = mul2(dx, dx);
            s = fma2(dy, dy, s);
            s = fma2(dz, dz, s);
            float lo, hi;
            unpack2(s, lo, hi);
            mn[r] = fminf(mn[r], fminf(lo, hi));
        }
    }
    if (cnt & 1) {  // scalar tail (defensive; CH and M are even for this problem)
        const float bxs = nx[cnt - 1], bys = ny[cnt - 1], bzs = nz[cnt - 1];
#pragma unroll
        for (int r = 0; r < RN; r++) {
            float axs, dummy;
            unpack2(ax[r], axs, dummy);
            float ays, azs;
            unpack2(ay[r], ays, dummy);
            unpack2(az[r], azs, dummy);
            (void)dummy;
            float dx = axs + bxs, dy = ays + bys, dz = azs + bzs;
            float s = dx * dx + dy * dy + dz * dz;
            mn[r] = fminf(mn[r], s);
        }
    }

    float* outMin = which ? g_min1 : g_min0;
#pragma unroll
    for (int r = 0; r < RN; r++) {
        if (nIdx[r] < Nq) {
            // nonneg floats: int-compare == float-compare; min is order-independent
            atomicMin((int*)&outMin[(size_t)b * Nq + nIdx[r]], __float_as_int(mn[r]));
        }
    }
}

// ---------- deterministic single-block reduction ----------
__global__ void reduce_kernel(float* __restrict__ out, int n0, int n1, float inv0, float inv1) {
    __shared__ float s[1024];
    const int tid = threadIdx.x;
    float acc = 0.f;
    for (int i = tid; i < n0; i += 1024) acc += sqrtf(g_min0[i]) * inv0;
    for (int i = tid; i < n1; i += 1024) acc += sqrtf(g_min1[i]) * inv1;
    s[tid] = acc;
    __syncthreads();
    for (int stride = 512; stride > 0; stride >>= 1) {
        if (tid < stride) s[tid] += s[tid + stride];
        __syncthreads();
    }
    if (tid == 0) out[0] = s[0];
}

extern "C" void kernel_launch(void* const* d_in, const int* in_sizes, int n_in,
                              void* d_out, int out_size) {
    const float* in1 = (const float*)d_in[0];  // [B, N, 3]
    const float* in2 = (const float*)d_in[1];  // [B, M, 3]
    const int B = 4, K = 3;
    const int N = in_sizes[0] / (B * K);
    const int M = in_sizes[1] / (B * K);

    const int initN = (B * N > B * M ? B * N : B * M);
    init_kernel<<<(initN + 255) / 256, 256>>>(B * M, B * N);

    // dist1: for each point of cloud1, min over cloud2
    dim3 g1((N + TN - 1) / TN, (M + CH - 1) / CH, B);
    pass_kernel<<<g1, TPB>>>(in1, in2, N, M, /*which=*/1);

    // dist0: for each point of cloud2, min over cloud1
    dim3 g0((M + TN - 1) / TN, (N + CH - 1) / CH, B);
    pass_kernel<<<g0, TPB>>>(in2, in1, M, N, /*which=*/0);

    reduce_kernel<<<1, 1024>>>((float*)d_out, B * M, B * N,
                               1.f / (float)(B * M), 1.f / (float)(B * N));
}

// round 3
// speedup vs baseline: 1.3881x; 1.3881x over previous
#include <cuda_runtime.h>
#include <math.h>
#include <float.h>

#define TPB 256
#define RN 4
#define QPB (TPB * 2 * RN)  // 2048 query points per block (2 per packed reg)
#define CH 222              // reference points staged per chunk
#define MAXPTS (4 * 8192)

typedef unsigned long long ull;

// Scratch (no cudaMalloc allowed). Holds clamped squared distances.
__device__ float g_min0[MAXPTS];  // for each point of cloud2: min over cloud1
__device__ float g_min1[MAXPTS];  // for each point of cloud1: min over cloud2
__device__ float g_part[128];

// ---------- packed f32x2 helpers ----------
union P2 {
    ull u;
    float2 f;
};

__device__ __forceinline__ ull pack2(float lo, float hi) {
    P2 p;
    p.f = make_float2(lo, hi);
    return p.u;
}
__device__ __forceinline__ ull fma2(ull a, ull b, ull c) {
    ull d;
    asm("fma.rn.f32x2 %0, %1, %2, %3;" : "=l"(d) : "l"(a), "l"(b), "l"(c));
    return d;
}

// ---------- init ----------
__global__ void init_kernel(int n0, int n1) {
    int i = blockIdx.x * blockDim.x + threadIdx.x;
    if (i < n0) g_min0[i] = FLT_MAX;
    if (i < n1) g_min1[i] = FLT_MAX;
}

// ---------- main pass ----------
// For each query q in Q: min over refs r in chunk of t = (h_r - q.r), h_r = |r|^2/2.
// Writes clamped d^2 = max(0, 2*t_min + |q|^2) via atomicMin on float bits.
__global__ __launch_bounds__(TPB) void pass_kernel(const float* __restrict__ Q,
                                                   const float* __restrict__ R,
                                                   int Nq, int Mr, int which) {
    // Each ref staged as 4 duplicated float2s: (x,x)(y,y)(z,z)(h,h) = 32B
    __shared__ __align__(16) float2 sref[CH * 4];

    const int b = blockIdx.z;
    const int mStart = blockIdx.y * CH;
    int cnt = Mr - mStart;
    if (cnt > CH) cnt = CH;
    if (cnt < 0) cnt = 0;
    const int tid = threadIdx.x;

    for (int i = tid; i < cnt; i += TPB) {
        const float* p = R + ((size_t)b * Mr + mStart + i) * 3;
        float x = p[0], y = p[1], z = p[2];
        float h = 0.5f * (x * x + y * y + z * z);
        sref[i * 4 + 0] = make_float2(x, x);
        sref[i * 4 + 1] = make_float2(y, y);
        sref[i * 4 + 2] = make_float2(z, z);
        sref[i * 4 + 3] = make_float2(h, h);
    }
    __syncthreads();

    // Each thread owns RN pairs of consecutive queries. Store NEGATED coords
    // so t = fma(-q, r, h) accumulates h - q.r directly.
    const int nBase = blockIdx.x * QPB;
    ull aqx[RN], aqy[RN], aqz[RN];
    float q2lo[RN], q2hi[RN], mnlo[RN], mnhi[RN];
    int n0s[RN];
#pragma unroll
    for (int r = 0; r < RN; r++) {
        const int n0 = nBase + (r * TPB + tid) * 2;
        n0s[r] = n0;
        float x0 = 0.f, y0 = 0.f, z0 = 0.f, x1 = 0.f, y1 = 0.f, z1 = 0.f;
        if (n0 < Nq) {
            const float* p = Q + ((size_t)b * Nq + n0) * 3;
            x0 = p[0]; y0 = p[1]; z0 = p[2];
        }
        if (n0 + 1 < Nq) {
            const float* p = Q + ((size_t)b * Nq + n0 + 1) * 3;
            x1 = p[0]; y1 = p[1]; z1 = p[2];
        }
        aqx[r] = pack2(-x0, -x1);
        aqy[r] = pack2(-y0, -y1);
        aqz[r] = pack2(-z0, -z1);
        q2lo[r] = x0 * x0 + y0 * y0 + z0 * z0;
        q2hi[r] = x1 * x1 + y1 * y1 + z1 * z1;
        mnlo[r] = FLT_MAX;
        mnhi[r] = FLT_MAX;
    }

    const ull* sp = (const ull*)sref;
#pragma unroll 2
    for (int j = 0; j < cnt; j++) {
        const ull bx = sp[j * 4 + 0];  // LDS.64, uniform-address broadcast
        const ull by = sp[j * 4 + 1];
        const ull bz = sp[j * 4 + 2];
        const ull h2 = sp[j * 4 + 3];
#pragma unroll
        for (int r = 0; r < RN; r++) {
            ull t = fma2(aqz[r], bz, h2);
            t = fma2(aqy[r], by, t);
            t = fma2(aqx[r], bx, t);
            P2 p;
            p.u = t;
            mnlo[r] = fminf(mnlo[r], p.f.x);
            mnhi[r] = fminf(mnhi[r], p.f.y);
        }
    }

    float* outMin = which ? g_min1 : g_min0;
#pragma unroll
    for (int r = 0; r < RN; r++) {
        float dlo = fmaxf(0.f, fmaf(2.f, mnlo[r], q2lo[r]));
        float dhi = fmaxf(0.f, fmaf(2.f, mnhi[r], q2hi[r]));
        const int n0 = n0s[r];
        // nonneg floats: int-min == float-min; min is order-independent -> deterministic
        if (n0 < Nq)
            atomicMin((int*)&outMin[(size_t)b * Nq + n0], __float_as_int(dlo));
        if (n0 + 1 < Nq)
            atomicMin((int*)&outMin[(size_t)b * Nq + n0 + 1], __float_as_int(dhi));
    }
}

// ---------- two-stage deterministic reduction ----------
__global__ void reduce1_kernel(int len0, int len1, float inv0, float inv1) {
    const int bid = blockIdx.x;  // 0..63 -> g_min0, 64..127 -> g_min1
    const bool first = bid < 64;
    const float* src = first ? g_min0 : g_min1;
    const int len = first ? len0 : len1;
    const float inv = first ? inv0 : inv1;
    const int lb = first ? bid : bid - 64;
    const int slice = (len + 63) / 64;
    const int start = lb * slice;
    int end = start + slice;
    if (end > len) end = len;

    float acc = 0.f;
    for (int i = start + threadIdx.x; i < end; i += 256) acc += sqrtf(src[i]) * inv;

    __shared__ float s[256];
    s[threadIdx.x] = acc;
    __syncthreads();
    for (int st = 128; st > 0; st >>= 1) {
        if (threadIdx.x < st) s[threadIdx.x] += s[threadIdx.x + st];
        __syncthreads();
    }
    if (threadIdx.x == 0) g_part[bid] = s[0];
}

__global__ void reduce2_kernel(float* __restrict__ out) {
    __shared__ float s[128];
    s[threadIdx.x] = g_part[threadIdx.x];
    __syncthreads();
    for (int st = 64; st > 0; st >>= 1) {
        if (threadIdx.x < st) s[threadIdx.x] += s[threadIdx.x + st];
        __syncthreads();
    }
    if (threadIdx.x == 0) out[0] = s[0];
}

extern "C" void kernel_launch(void* const* d_in, const int* in_sizes, int n_in,
                              void* d_out, int out_size) {
    const float* in1 = (const float*)d_in[0];  // [B, N, 3]
    const float* in2 = (const float*)d_in[1];  // [B, M, 3]
    const int B = 4, K = 3;
    const int N = in_sizes[0] / (B * K);
    const int M = in_sizes[1] / (B * K);

    const int initN = (B * N > B * M ? B * N : B * M);
    init_kernel<<<(initN + 255) / 256, 256>>>(B * M, B * N);

    // dist1: for each point of cloud1, min over cloud2
    dim3 g1((N + QPB - 1) / QPB, (M + CH - 1) / CH, B);
    pass_kernel<<<g1, TPB>>>(in1, in2, N, M, /*which=*/1);

    // dist0: for each point of cloud2, min over cloud1
    dim3 g0((M + QPB - 1) / QPB, (N + CH - 1) / CH, B);
    pass_kernel<<<g0, TPB>>>(in2, in1, M, N, /*which=*/0);

    reduce1_kernel<<<128, 256>>>(B * M, B * N, 1.f / (float)(B * M), 1.f / (float)(B * N));
    reduce2_kernel<<<1, 128>>>((float*)d_out);
}

// round 4
// speedup vs baseline: 1.4821x; 1.0677x over previous
#include <cuda_runtime.h>
#include <math.h>
#include <float.h>

#define TPB 256
#define RN 8
#define QPB (TPB * 2 * RN)  // 4096 query points per block (2 per packed reg)
#define CH 222              // reference points staged per chunk
#define MAXPTS (4 * 8192)

typedef unsigned long long ull;

// Scratch (no cudaMalloc allowed). Holds min DISTANCES (already sqrt'd).
__device__ float g_min0[MAXPTS];  // for each point of cloud2: min over cloud1
__device__ float g_min1[MAXPTS];  // for each point of cloud1: min over cloud2
__device__ float g_part[128];

// ---------- packed f32x2 helpers ----------
union P2 {
    ull u;
    float2 f;
};

__device__ __forceinline__ ull pack2(float lo, float hi) {
    P2 p;
    p.f = make_float2(lo, hi);
    return p.u;
}
__device__ __forceinline__ ull fma2(ull a, ull b, ull c) {
    ull d;
    asm("fma.rn.f32x2 %0, %1, %2, %3;" : "=l"(d) : "l"(a), "l"(b), "l"(c));
    return d;
}

// ---------- init ----------
__global__ void init_kernel(int n0, int n1) {
    int i = blockIdx.x * blockDim.x + threadIdx.x;
    if (i < n0) g_min0[i] = FLT_MAX;
    if (i < n1) g_min1[i] = FLT_MAX;
}

// ---------- main pass ----------
// For each query q: min over refs r in chunk of t = (h_r - q.r), h_r = |r|^2/2.
// Epilogue: d = sqrt(max(0, 2*t_min + |q|^2)), atomicMin on float bits.
__global__ __launch_bounds__(TPB, 2) void pass_kernel(const float* __restrict__ Q,
                                                      const float* __restrict__ R,
                                                      int Nq, int Mr, int which) {
    // Each ref staged as 4 duplicated float2s: (x,x)(y,y)(z,z)(h,h) = 32B
    __shared__ __align__(16) float2 sref[CH * 4];

    const int b = blockIdx.z;
    const int mStart = blockIdx.y * CH;
    int cnt = Mr - mStart;
    if (cnt > CH) cnt = CH;
    if (cnt < 0) cnt = 0;
    const int tid = threadIdx.x;

    for (int i = tid; i < cnt; i += TPB) {
        const float* p = R + ((size_t)b * Mr + mStart + i) * 3;
        float x = p[0], y = p[1], z = p[2];
        float h = 0.5f * (x * x + y * y + z * z);
        sref[i * 4 + 0] = make_float2(x, x);
        sref[i * 4 + 1] = make_float2(y, y);
        sref[i * 4 + 2] = make_float2(z, z);
        sref[i * 4 + 3] = make_float2(h, h);
    }
    __syncthreads();

    // Each thread owns RN pairs of consecutive queries, coords NEGATED so
    // t = fma(-q, r, h) accumulates h - q.r directly.
    const int nBase = blockIdx.x * QPB;
    ull aqx[RN], aqy[RN], aqz[RN];
    float mnlo[RN], mnhi[RN];
#pragma unroll
    for (int r = 0; r < RN; r++) {
        const int n0 = nBase + (r * TPB + tid) * 2;
        float x0 = 0.f, y0 = 0.f, z0 = 0.f, x1 = 0.f, y1 = 0.f, z1 = 0.f;
        if (n0 < Nq) {
            const float* p = Q + ((size_t)b * Nq + n0) * 3;
            x0 = p[0]; y0 = p[1]; z0 = p[2];
        }
        if (n0 + 1 < Nq) {
            const float* p = Q + ((size_t)b * Nq + n0 + 1) * 3;
            x1 = p[0]; y1 = p[1]; z1 = p[2];
        }
        aqx[r] = pack2(-x0, -x1);
        aqy[r] = pack2(-y0, -y1);
        aqz[r] = pack2(-z0, -z1);
        mnlo[r] = FLT_MAX;
        mnhi[r] = FLT_MAX;
    }

    const ull* sp = (const ull*)sref;
#pragma unroll 2
    for (int j = 0; j < cnt; j++) {
        const ull bx = sp[j * 4 + 0];  // LDS.64, uniform-address broadcast
        const ull by = sp[j * 4 + 1];
        const ull bz = sp[j * 4 + 2];
        const ull h2 = sp[j * 4 + 3];
#pragma unroll
        for (int r = 0; r < RN; r++) {
            ull t = fma2(aqz[r], bz, h2);
            t = fma2(aqy[r], by, t);
            t = fma2(aqx[r], bx, t);
            P2 p;
            p.u = t;
            mnlo[r] = fminf(mnlo[r], p.f.x);
            mnhi[r] = fminf(mnhi[r], p.f.y);
        }
    }

    float* outMin = which ? g_min1 : g_min0;
#pragma unroll
    for (int r = 0; r < RN; r++) {
        // Recompute |q|^2 from the negated packed coords (squares unchanged).
        P2 px, py, pz;
        px.u = aqx[r]; py.u = aqy[r]; pz.u = aqz[r];
        float q2lo = px.f.x * px.f.x + py.f.x * py.f.x + pz.f.x * pz.f.x;
        float q2hi = px.f.y * px.f.y + py.f.y * py.f.y + pz.f.y * pz.f.y;
        float dlo = sqrtf(fmaxf(0.f, fmaf(2.f, mnlo[r], q2lo)));
        float dhi = sqrtf(fmaxf(0.f, fmaf(2.f, mnhi[r], q2hi)));
        const int n0 = nBase + (r * TPB + tid) * 2;
        // nonneg floats: int-min == float-min; min is order-independent -> deterministic
        if (n0 < Nq)
            atomicMin((int*)&outMin[(size_t)b * Nq + n0], __float_as_int(dlo));
        if (n0 + 1 < Nq)
            atomicMin((int*)&outMin[(size_t)b * Nq + n0 + 1], __float_as_int(dhi));
    }
}

// ---------- two-stage deterministic reduction (arrays hold d already) ----------
__global__ void reduce1_kernel(int len0, int len1, float inv0, float inv1) {
    const int bid = blockIdx.x;  // 0..63 -> g_min0, 64..127 -> g_min1
    const bool first = bid < 64;
    const float* src = first ? g_min0 : g_min1;
    const int len = first ? len0 : len1;
    const float inv = first ? inv0 : inv1;
    const int lb = first ? bid : bid - 64;
    const int slice = (len + 63) / 64;
    const int start = lb * slice;
    int end = start + slice;
    if (end > len) end = len;

    float acc = 0.f;
    for (int i = start + threadIdx.x; i < end; i += 256) acc += src[i] * inv;

#pragma unroll
    for (int off = 16; off > 0; off >>= 1)
        acc += __shfl_down_sync(0xFFFFFFFFu, acc, off);

    __shared__ float s[8];
    if ((threadIdx.x & 31) == 0) s[threadIdx.x >> 5] = acc;
    __syncthreads();
    if (threadIdx.x < 8) {
        float v = s[threadIdx.x];
#pragma unroll
        for (int off = 4; off > 0; off >>= 1)
            v += __shfl_down_sync(0xFFu, v, off);
        if (threadIdx.x == 0) g_part[bid] = v;
    }
}

__global__ void reduce2_kernel(float* __restrict__ out) {
    __shared__ float s[128];
    s[threadIdx.x] = g_part[threadIdx.x];
    __syncthreads();
    for (int st = 64; st > 0; st >>= 1) {
        if (threadIdx.x < st) s[threadIdx.x] += s[threadIdx.x + st];
        __syncthreads();
    }
    if (threadIdx.x == 0) out[0] = s[0];
}

extern "C" void kernel_launch(void* const* d_in, const int* in_sizes, int n_in,
                              void* d_out, int out_size) {
    const float* in1 = (const float*)d_in[0];  // [B, N, 3]
    const float* in2 = (const float*)d_in[1];  // [B, M, 3]
    const int B = 4, K = 3;
    const int N = in_sizes[0] / (B * K);
    const int M = in_sizes[1] / (B * K);

    const int initN = (B * N > B * M ? B * N : B * M);
    init_kernel<<<(initN + 255) / 256, 256>>>(B * M, B * N);

    // dist1: for each point of cloud1, min over cloud2
    dim3 g1((N + QPB - 1) / QPB, (M + CH - 1) / CH, B);
    pass_kernel<<<g1, TPB>>>(in1, in2, N, M, /*which=*/1);

    // dist0: for each point of cloud2, min over cloud1
    dim3 g0((M + QPB - 1) / QPB, (N + CH - 1) / CH, B);
    pass_kernel<<<g0, TPB>>>(in2, in1, M, N, /*which=*/0);

    reduce1_kernel<<<128, 256>>>(B * M, B * N, 1.f / (float)(B * M), 1.f / (float)(B * N));
    reduce2_kernel<<<1, 128>>>((float*)d_out);
}

// round 5
// speedup vs baseline: 1.5187x; 1.0247x over previous
#include <cuda_runtime.h>
#include <math.h>
#include <float.h>

#define TPB 256
#define RN 8
#define QPB (TPB * 2 * RN)  // 4096 query points per block (2 per packed reg)
#define CH 222              // reference points staged per chunk
#define MAXPTS (4 * 8192)

typedef unsigned long long ull;

// Scratch (no cudaMalloc). Arrays hold u = half squared distance; d = sqrt(2u).
__device__ float g_min0[MAXPTS];  // for each point of cloud2: min_u over cloud1
__device__ float g_min1[MAXPTS];  // for each point of cloud1: min_u over cloud2
__device__ float g_part[128];

union P2 {
    ull u;
    float2 f;
};

__device__ __forceinline__ ull pack2(float lo, float hi) {
    P2 p;
    p.f = make_float2(lo, hi);
    return p.u;
}
__device__ __forceinline__ ull fma2(ull a, ull b, ull c) {
    ull d;
    asm("fma.rn.f32x2 %0, %1, %2, %3;" : "=l"(d) : "l"(a), "l"(b), "l"(c));
    return d;
}
__device__ __forceinline__ ull add2(ull a, ull b) {
    ull d;
    asm("add.rn.f32x2 %0, %1, %2;" : "=l"(d) : "l"(a), "l"(b));
    return d;
}

__global__ void init_kernel(int n0, int n1) {
    int i = blockIdx.x * blockDim.x + threadIdx.x;
    if (i < n0) g_min0[i] = FLT_MAX;
    if (i < n1) g_min1[i] = FLT_MAX;
}

// ---------- fused pass: each pair distance computed ONCE, feeds BOTH minima ----------
// u(q,r) = g_q + h_r - q.r = |q-r|^2 / 2  (symmetric).
// n-direction: per-thread running min over refs  -> g_min1.
// m-direction: per-ref fold over the block's queries via warp shuffle -> g_min0.
__global__ __launch_bounds__(TPB, 2) void fused_kernel(const float* __restrict__ Q,
                                                       const float* __restrict__ R,
                                                       int Nq, int Mr) {
    __shared__ __align__(16) float2 sref[CH * 4];  // (x,x)(y,y)(z,z)(h,h) per ref

    const int b = blockIdx.z;
    const int mStart = blockIdx.y * CH;
    int cnt = Mr - mStart;
    if (cnt > CH) cnt = CH;
    if (cnt < 0) cnt = 0;
    const int tid = threadIdx.x;

    for (int i = tid; i < cnt; i += TPB) {
        const float* p = R + ((size_t)b * Mr + mStart + i) * 3;
        float x = p[0], y = p[1], z = p[2];
        float h = 0.5f * (x * x + y * y + z * z);
        sref[i * 4 + 0] = make_float2(x, x);
        sref[i * 4 + 1] = make_float2(y, y);
        sref[i * 4 + 2] = make_float2(z, z);
        sref[i * 4 + 3] = make_float2(h, h);
    }
    __syncthreads();

    const int nBase = blockIdx.x * QPB;
    ull aqx[RN], aqy[RN], aqz[RN], gq[RN];
    float mnlo[RN], mnhi[RN];
#pragma unroll
    for (int r = 0; r < RN; r++) {
        const int n0 = nBase + (r * TPB + tid) * 2;
        // Pad queries get g=1e30 so their u never wins the m-direction min.
        float x0 = 0.f, y0 = 0.f, z0 = 0.f, g0 = 1e30f;
        float x1 = 0.f, y1 = 0.f, z1 = 0.f, g1 = 1e30f;
        if (n0 < Nq) {
            const float* p = Q + ((size_t)b * Nq + n0) * 3;
            x0 = p[0]; y0 = p[1]; z0 = p[2];
            g0 = 0.5f * (x0 * x0 + y0 * y0 + z0 * z0);
        }
        if (n0 + 1 < Nq) {
            const float* p = Q + ((size_t)b * Nq + n0 + 1) * 3;
            x1 = p[0]; y1 = p[1]; z1 = p[2];
            g1 = 0.5f * (x1 * x1 + y1 * y1 + z1 * z1);
        }
        aqx[r] = pack2(-x0, -x1);
        aqy[r] = pack2(-y0, -y1);
        aqz[r] = pack2(-z0, -z1);
        gq[r] = pack2(g0, g1);
        mnlo[r] = FLT_MAX;
        mnhi[r] = FLT_MAX;
    }

    const ull* sp = (const ull*)sref;
    for (int j = 0; j < cnt; j++) {
        const ull bx = sp[j * 4 + 0];  // LDS.64 uniform-address broadcast
        const ull by = sp[j * 4 + 1];
        const ull bz = sp[j * 4 + 2];
        const ull h2 = sp[j * 4 + 3];
        float fold[RN];
#pragma unroll
        for (int r = 0; r < RN; r++) {
            ull t = fma2(aqz[r], bz, gq[r]);
            t = fma2(aqy[r], by, t);
            t = fma2(aqx[r], bx, t);
            ull u = add2(t, h2);
            P2 p;
            p.u = u;
            mnlo[r] = fminf(mnlo[r], p.f.x);
            mnhi[r] = fminf(mnhi[r], p.f.y);
            fold[r] = fminf(p.f.x, p.f.y);
        }
        // m-direction: min over this thread's 16 queries, then warp, then global.
        float m01 = fminf(fold[0], fold[1]);
        float m23 = fminf(fold[2], fold[3]);
        float m45 = fminf(fold[4], fold[5]);
        float m67 = fminf(fold[6], fold[7]);
        float mloc = fminf(fminf(m01, m23), fminf(m45, m67));
#pragma unroll
        for (int off = 16; off > 0; off >>= 1)
            mloc = fminf(mloc, __shfl_xor_sync(0xFFFFFFFFu, mloc, off));
        if ((tid & 31) == 0)
            atomicMin((int*)&g_min0[(size_t)b * Mr + mStart + j], __float_as_int(mloc));
    }

    // n-direction epilogue.
#pragma unroll
    for (int r = 0; r < RN; r++) {
        const int n0 = nBase + (r * TPB + tid) * 2;
        if (n0 < Nq)
            atomicMin((int*)&g_min1[(size_t)b * Nq + n0], __float_as_int(mnlo[r]));
        if (n0 + 1 < Nq)
            atomicMin((int*)&g_min1[(size_t)b * Nq + n0 + 1], __float_as_int(mnhi[r]));
    }
}

// ---------- two-stage deterministic reduction: d = sqrt(2u) ----------
__global__ void reduce1_kernel(int len0, int len1, float inv0, float inv1) {
    const int bid = blockIdx.x;  // 0..63 -> g_min0, 64..127 -> g_min1
    const bool first = bid < 64;
    const float* src = first ? g_min0 : g_min1;
    const int len = first ? len0 : len1;
    const float inv = first ? inv0 : inv1;
    const int lb = first ? bid : bid - 64;
    const int slice = (len + 63) / 64;
    const int start = lb * slice;
    int end = start + slice;
    if (end > len) end = len;

    float acc = 0.f;
    for (int i = start + threadIdx.x; i < end; i += 256)
        acc += sqrtf(2.f * src[i]) * inv;

#pragma unroll
    for (int off = 16; off > 0; off >>= 1)
        acc += __shfl_down_sync(0xFFFFFFFFu, acc, off);

    __shared__ float s[8];
    if ((threadIdx.x & 31) == 0) s[threadIdx.x >> 5] = acc;
    __syncthreads();
    if (threadIdx.x < 8) {
        float v = s[threadIdx.x];
#pragma unroll
        for (int off = 4; off > 0; off >>= 1)
            v += __shfl_down_sync(0xFFu, v, off);
        if (threadIdx.x == 0) g_part[bid] = v;
    }
}

__global__ void reduce2_kernel(float* __restrict__ out) {
    __shared__ float s[128];
    s[threadIdx.x] = g_part[threadIdx.x];
    __syncthreads();
    for (int st = 64; st > 0; st >>= 1) {
        if (threadIdx.x < st) s[threadIdx.x] += s[threadIdx.x + st];
        __syncthreads();
    }
    if (threadIdx.x == 0) out[0] = s[0];
}

extern "C" void kernel_launch(void* const* d_in, const int* in_sizes, int n_in,
                              void* d_out, int out_size) {
    const float* in1 = (const float*)d_in[0];  // [B, N, 3] cloud1
    const float* in2 = (const float*)d_in[1];  // [B, M, 3] cloud2
    const int B = 4, K = 3;
    const int N = in_sizes[0] / (B * K);
    const int M = in_sizes[1] / (B * K);

    const int initN = (B * N > B * M ? B * N : B * M);
    init_kernel<<<(initN + 255) / 256, 256>>>(B * M, B * N);

    // One fused pass: queries = cloud1 (n-dir -> g_min1), refs = cloud2 (m-dir -> g_min0).
    dim3 g((N + QPB - 1) / QPB, (M + CH - 1) / CH, B);
    fused_kernel<<<g, TPB>>>(in1, in2, N, M);

    reduce1_kernel<<<128, 256>>>(B * M, B * N, 1.f / (float)(B * M), 1.f / (float)(B * N));
    reduce2_kernel<<<1, 128>>>((float*)d_out);
}